// round 14
// baseline (speedup 1.0000x reference)
#include <cuda_runtime.h>
#include <cuda_bf16.h>
#include <stdint.h>
#include <math.h>

// Problem constants
#define BN 8
#define CN 256
#define ON 256
#define HN 64
#define WN 64
#define HW 4096
#define K2 9
#define DGN 4
#define CGN 64
#define KD 2304          // CN*K2 (GEMM reduction dim)
#define GN_GROUPS 32
#define GRP_ELEMS 32768
#define EPS 1e-5f

// Fused tiling: BM=256 (all of M, one CTA per n-tile), BNT=64, BK=32
#define BM 256
#define BNT 64
#define BK 32
#define NCH (KD / BK)        // 72
#define ROWB 80              // padded SMEM row stride (bytes) for 32 bf16
#define T_A (BM * ROWB)      // 20480 per A tile (hi or lo)
#define T_Bt (BNT * ROWB)    // 5120 per B tile (hi or lo)
#define A_STAGE (2 * T_A)    // 40960
#define B_BUF (2 * T_Bt)     // 10240
#define NSTAGE 3
// SMEM layout offsets
#define OFF_A 0                          // 3 * 40960 = 122880
#define OFF_B (3 * A_STAGE)              // 122880 .. +20480 = 143360
#define OFF_W (OFF_B + 2 * B_BUF)        // 143360 : float[4*2304] = 36864
#define OFF_I (OFF_W + 4 * 2304 * 4)     // 180224 : u16[4*2304] = 18432
#define OFF_K (OFF_I + 4 * 2304 * 2)     // 198656 : u16[2304]  = 4608
#define FUSED_SMEM (OFF_K + 2304 * 2 + 64)   // 203328

// ---------------------------------------------------------------------------
// Device scratch (col buffers eliminated!)
// ---------------------------------------------------------------------------
__device__ __nv_bfloat16 g_wh[(size_t)ON * KD];
__device__ __nv_bfloat16 g_wl[(size_t)ON * KD];
__device__ float g_mu[BN * GN_GROUPS];
__device__ float g_rstd[BN * GN_GROUPS];

// ---------------------------------------------------------------------------
// PTX helpers (stable sm_80+ features only)
// ---------------------------------------------------------------------------
__device__ __forceinline__ uint32_t smem_u32(const void* p) {
    uint32_t a;
    asm("{ .reg .u64 t; cvta.to.shared.u64 t, %1; cvt.u32.u64 %0, t; }"
        : "=r"(a) : "l"(p));
    return a;
}
__device__ __forceinline__ void cp16(uint32_t s, const void* g) {
    asm volatile("cp.async.cg.shared.global [%0], [%1], 16;"
                 :: "r"(s), "l"(g) : "memory");
}
#define CP_COMMIT() asm volatile("cp.async.commit_group;" ::: "memory")
#define CP_WAIT(n)  asm volatile("cp.async.wait_group %0;" :: "n"(n) : "memory")

__device__ __forceinline__ void ldm_x4(uint32_t* r, uint32_t addr) {
    asm volatile("ldmatrix.sync.aligned.m8n8.x4.shared.b16 {%0,%1,%2,%3}, [%4];"
                 : "=r"(r[0]), "=r"(r[1]), "=r"(r[2]), "=r"(r[3]) : "r"(addr));
}
__device__ __forceinline__ void mma_bf16(float* c, const uint32_t* a,
                                         const uint32_t* b) {
    asm volatile(
        "mma.sync.aligned.m16n8k16.row.col.f32.bf16.bf16.f32 "
        "{%0,%1,%2,%3}, {%4,%5,%6,%7}, {%8,%9}, {%0,%1,%2,%3};"
        : "+f"(c[0]), "+f"(c[1]), "+f"(c[2]), "+f"(c[3])
        : "r"(a[0]), "r"(a[1]), "r"(a[2]), "r"(a[3]), "r"(b[0]), "r"(b[1]));
}

// ---------------------------------------------------------------------------
// Kernel A: split weights into bf16 hi/lo. w flat [O][KD], kd = c*9+ky*3+kx.
// ---------------------------------------------------------------------------
__global__ void wsplit_kernel(const float* __restrict__ w)
{
    int i = blockIdx.x * blockDim.x + threadIdx.x;
    float v = w[i];
    __nv_bfloat16 h = __float2bfloat16(v);
    __nv_bfloat16 l = __float2bfloat16(v - __bfloat162float(h));
    g_wh[i] = h;
    g_wl[i] = l;
}

// ---------------------------------------------------------------------------
// Fused deformable-conv GEMM:
// out[b][m][hw0+n] = sum_kd W[m][kd] * col(b, hw0+n, kd), col computed on the
// fly per BK-chunk into SMEM (bit-identical to validated im2col v3/v5 math).
// One CTA per (b, 64-hw tile) covers ALL M=256 -> samples computed once.
// A: race-free 3-stage cp.async (R13-validated ordering).
// B: double-buffered SMEM production; produce(ch+1) placed after mma(ch);
//    writes to buf (ch-1)&1 whose readers all passed the top barrier.
// ---------------------------------------------------------------------------
__global__ void __launch_bounds__(512, 1)
fused_dconv_kernel(const float* __restrict__ x,
                   const float* __restrict__ x_off,
                   const float* __restrict__ w_offset,
                   float* __restrict__ out)
{
    extern __shared__ char smem[];
    const uint32_t sb = smem_u32(smem);
    const int tid = threadIdx.x;
    const int wid = tid >> 5, lane = tid & 31;
    const int warp_m = wid & 7;          // 8 m-warps x 32 rows = 256
    const int warp_n = wid >> 3;         // 2 n-warps x 32 cols = 64
    const int hw0 = blockIdx.x * BNT;
    const int b   = blockIdx.y;

    float*    s_w = (float*)(smem + OFF_W);      // [4][2304] bilinear weights
    uint16_t* s_i = (uint16_t*)(smem + OFF_I);   // [4][2304] gather indices
    uint16_t* s_k = (uint16_t*)(smem + OFF_K);   // [2304] kd -> (cglob, gk)

    // --- Phase P1: bilinear params, p = gk*64 + hwl (validated v5 math) ---
    for (int p = tid; p < 2304; p += 512) {
        int hwl = p & 63;
        int gk  = p >> 6;                // 0..35
        int g = gk / 9, k = gk - 9 * g;
        int hw = hw0 + hwl;
        int h = hw >> 6, w = hw & 63;

        const float* xo = x_off + (size_t)b * 4 * HW + hw;
        float o0 = xo[0], o1 = xo[HW], o2 = xo[2 * HW], o3 = xo[3 * HW];
        const float* wo = w_offset + (size_t)((g * K2 + k) * 2) * 4;
        float offy = wo[0] * o0 + wo[1] * o1 + wo[2] * o2 + wo[3] * o3;
        float offx = wo[4] * o0 + wo[5] * o1 + wo[6] * o2 + wo[7] * o3;

        float py = (float)(h + k / 3 - 1) + offy;
        float px = (float)(w + k % 3 - 1) + offx;
        float fy = floorf(py), fx = floorf(px);
        int y0 = (int)fy, x0 = (int)fx, y1 = y0 + 1, x1 = x0 + 1;
        float wy = py - fy, wx = px - fx;

        float my0 = (y0 >= 0 && y0 < HN) ? 1.f : 0.f;
        float my1 = (y1 >= 0 && y1 < HN) ? 1.f : 0.f;
        float mx0 = (x0 >= 0 && x0 < WN) ? 1.f : 0.f;
        float mx1 = (x1 >= 0 && x1 < WN) ? 1.f : 0.f;
        int y0c = min(max(y0, 0), HN - 1), y1c = min(max(y1, 0), HN - 1);
        int x0c = min(max(x0, 0), WN - 1), x1c = min(max(x1, 0), WN - 1);

        s_i[0 * 2304 + p] = (uint16_t)(y0c * WN + x0c);
        s_i[1 * 2304 + p] = (uint16_t)(y0c * WN + x1c);
        s_i[2 * 2304 + p] = (uint16_t)(y1c * WN + x0c);
        s_i[3 * 2304 + p] = (uint16_t)(y1c * WN + x1c);
        s_w[0 * 2304 + p] = (1.f - wy) * (1.f - wx) * my0 * mx0;
        s_w[1 * 2304 + p] = (1.f - wy) * wx          * my0 * mx1;
        s_w[2 * 2304 + p] = wy * (1.f - wx)          * my1 * mx0;
        s_w[3 * 2304 + p] = wy * wx                  * my1 * mx1;
    }
    // kd -> packed (cglob, gk) map: kd = g*576 + c*9 + k, cglob = g*64+c
    for (int kd = tid; kd < KD; kd += 512) {
        int g = kd / 576, rem = kd - 576 * g;
        int c = rem / 9,  k   = rem - 9 * c;
        s_k[kd] = (uint16_t)(((g * 64 + c) << 6) | (g * 9 + k));
    }
    __syncthreads();

    const float* xb = x + (size_t)b * CN * HW;

    // --- B producer: 2048 values (64 hw x 32 kd) x hi/lo per chunk ---
    auto produceB = [&](int ch, int buf) {
        uint32_t bb = sb + OFF_B + buf * B_BUF;
        #pragma unroll
        for (int j = 0; j < 4; j++) {
            int kdl = (tid >> 6) + 8 * j;        // warp-uniform
            int hwl = tid & 63;
            int kd  = ch * BK + kdl;
            int m   = s_k[kd];
            int cg  = m >> 6, gk = m & 63;
            int p   = gk * 64 + hwl;
            const float* xc = xb + (size_t)cg * HW;
            float v = s_w[p]            * xc[s_i[p]]
                    + s_w[2304 + p]     * xc[s_i[2304 + p]]
                    + s_w[4608 + p]     * xc[s_i[4608 + p]]
                    + s_w[6912 + p]     * xc[s_i[6912 + p]];
            __nv_bfloat16 hb = __float2bfloat16(v);
            __nv_bfloat16 lb = __float2bfloat16(v - __bfloat162float(hb));
            uint32_t off = (uint32_t)(buf * B_BUF + hwl * ROWB + kdl * 2);
            *(uint16_t*)(smem + OFF_B + off)        = __bfloat16_as_ushort(hb);
            *(uint16_t*)(smem + OFF_B + off + T_Bt) = __bfloat16_as_ushort(lb);
        }
        (void)bb;
    };

    // --- A loader: 256 rows x 4 16B-units, hi+lo, one stage ---
    auto loadA = [&](int ch, int stg) {
        const int k0 = ch * BK;
        uint32_t st = sb + OFF_A + stg * A_STAGE;
        #pragma unroll
        for (int j = 0; j < 2; j++) {
            int u = tid + j * 512;
            int row = u >> 2, cs = u & 3;
            cp16(st + row * ROWB + cs * 16,
                 g_wh + (size_t)row * KD + k0 + cs * 8);
            cp16(st + T_A + row * ROWB + cs * 16,
                 g_wl + (size_t)row * KD + k0 + cs * 8);
        }
        CP_COMMIT();
    };

    float c[2][4][4];
    #pragma unroll
    for (int i = 0; i < 2; i++)
        #pragma unroll
        for (int j = 0; j < 4; j++)
            #pragma unroll
            for (int q = 0; q < 4; q++) c[i][j][q] = 0.f;

    // Prologue
    loadA(0, 0);
    loadA(1, 1);
    produceB(0, 0);

    for (int ch = 0; ch < NCH; ch++) {
        // 1) A(ch) landed
        if (ch + 1 < NCH) { CP_WAIT(1); } else { CP_WAIT(0); }
        // 2) barrier: B(ch) visible; all warps done reading stage/buf of ch-1
        __syncthreads();
        // 3) refill A stage (ch+2)%3 == (ch-1)%3 (safe after barrier)
        if (ch + 2 < NCH) loadA(ch + 2, (ch + 2) % NSTAGE);

        // 4) mma on A stage ch%3, B buf ch&1 (validated per-warp code)
        const uint32_t st = sb + OFF_A + (ch % NSTAGE) * A_STAGE;
        const uint32_t bbase = sb + OFF_B + (ch & 1) * B_BUF;
        #pragma unroll
        for (int ks = 0; ks < 2; ks++) {
            uint32_t a_off = (uint32_t)((warp_m * 32 + (lane & 15)) * ROWB
                                        + ks * 32 + ((lane >> 4) << 4));
            uint32_t ah[2][4], al[2][4];
            #pragma unroll
            for (int mf = 0; mf < 2; mf++) {
                ldm_x4(ah[mf], st + a_off + mf * 16 * ROWB);
                ldm_x4(al[mf], st + T_A + a_off + mf * 16 * ROWB);
            }
            uint32_t b_off = (uint32_t)((warp_n * 32 + (lane & 7) + ((lane >> 4) << 3)) * ROWB
                                        + ks * 32 + (((lane >> 3) & 1) << 4));
            uint32_t bh[4][2], bl[4][2];
            #pragma unroll
            for (int nfp = 0; nfp < 2; nfp++) {
                uint32_t r[4];
                ldm_x4(r, bbase + b_off + nfp * 16 * ROWB);
                bh[nfp * 2][0] = r[0]; bh[nfp * 2][1] = r[1];
                bh[nfp * 2 + 1][0] = r[2]; bh[nfp * 2 + 1][1] = r[3];
                ldm_x4(r, bbase + T_Bt + b_off + nfp * 16 * ROWB);
                bl[nfp * 2][0] = r[0]; bl[nfp * 2][1] = r[1];
                bl[nfp * 2 + 1][0] = r[2]; bl[nfp * 2 + 1][1] = r[3];
            }
            #pragma unroll
            for (int mf = 0; mf < 2; mf++)
                #pragma unroll
                for (int nf = 0; nf < 4; nf++) {
                    mma_bf16(c[mf][nf], ah[mf], bh[nf]);
                    mma_bf16(c[mf][nf], ah[mf], bl[nf]);
                    mma_bf16(c[mf][nf], al[mf], bh[nf]);
                }
        }

        // 5) produce B(ch+1) into buf (ch+1)&1 == (ch-1)&1 (readers passed
        //    the barrier in step 2; mma(ch) reads buf ch&1 — disjoint)
        if (ch + 1 < NCH) produceB(ch + 1, (ch + 1) & 1);
    }

    // Epilogue
    #pragma unroll
    for (int mf = 0; mf < 2; mf++)
        #pragma unroll
        for (int nf = 0; nf < 4; nf++) {
            int row = warp_m * 32 + mf * 16 + (lane >> 2);
            int col = hw0 + warp_n * 32 + nf * 8 + 2 * (lane & 3);
            float* op0 = out + ((size_t)(b * ON + row)) * HW + col;
            float* op1 = out + ((size_t)(b * ON + row + 8)) * HW + col;
            *(float2*)op0 = make_float2(c[mf][nf][0], c[mf][nf][1]);
            *(float2*)op1 = make_float2(c[mf][nf][2], c[mf][nf][3]);
        }
}

// ---------------------------------------------------------------------------
// GroupNorm stats + normalize (validated)
// ---------------------------------------------------------------------------
__global__ void gn_stats_kernel(const float* __restrict__ y)
{
    const int bg = blockIdx.x;
    const float* p = y + (size_t)bg * GRP_ELEMS;
    float s = 0.f, ss = 0.f;
    for (int i = threadIdx.x * 4; i < GRP_ELEMS; i += blockDim.x * 4) {
        float4 v = *(const float4*)(p + i);
        s  += v.x + v.y + v.z + v.w;
        ss += v.x * v.x + v.y * v.y + v.z * v.z + v.w * v.w;
    }
    #pragma unroll
    for (int off = 16; off > 0; off >>= 1) {
        s  += __shfl_down_sync(0xffffffffu, s,  off);
        ss += __shfl_down_sync(0xffffffffu, ss, off);
    }
    __shared__ float sh_s[8], sh_ss[8];
    int wid = threadIdx.x >> 5, lid = threadIdx.x & 31;
    if (lid == 0) { sh_s[wid] = s; sh_ss[wid] = ss; }
    __syncthreads();
    if (wid == 0) {
        s  = (lid < 8) ? sh_s[lid]  : 0.f;
        ss = (lid < 8) ? sh_ss[lid] : 0.f;
        #pragma unroll
        for (int off = 4; off > 0; off >>= 1) {
            s  += __shfl_down_sync(0xffffffffu, s,  off);
            ss += __shfl_down_sync(0xffffffffu, ss, off);
        }
        if (lid == 0) {
            float mu  = s * (1.f / GRP_ELEMS);
            float var = ss * (1.f / GRP_ELEMS) - mu * mu;
            g_mu[bg]   = mu;
            g_rstd[bg] = rsqrtf(var + EPS);
        }
    }
}

__global__ void gn_norm_kernel(float* __restrict__ y,
                               const float* __restrict__ gamma,
                               const float* __restrict__ beta)
{
    int idx = blockIdx.x * blockDim.x + threadIdx.x;
    int bg = idx >> 13;
    int c  = (idx >> 10) & 255;
    float mu = g_mu[bg];
    float r  = g_rstd[bg];
    float a  = r * gamma[c];
    float bb = beta[c] - mu * a;
    float4 v = *(float4*)(y + (size_t)idx * 4);
    v.x = fmaxf(fmaf(v.x, a, bb), 0.f);
    v.y = fmaxf(fmaf(v.y, a, bb), 0.f);
    v.z = fmaxf(fmaf(v.z, a, bb), 0.f);
    v.w = fmaxf(fmaf(v.w, a, bb), 0.f);
    *(float4*)(y + (size_t)idx * 4) = v;
}

// ---------------------------------------------------------------------------
// Launcher
// ---------------------------------------------------------------------------
extern "C" void kernel_launch(void* const* d_in, const int* in_sizes, int n_in,
                              void* d_out, int out_size)
{
    const float* x        = (const float*)d_in[0];
    const float* x_off    = (const float*)d_in[1];
    const float* w_offset = (const float*)d_in[2];
    const float* w_deform = (const float*)d_in[3];
    const float* gamma    = (const float*)d_in[4];
    const float* beta     = (const float*)d_in[5];
    float* out = (float*)d_out;

    cudaFuncSetAttribute(fused_dconv_kernel,
                         cudaFuncAttributeMaxDynamicSharedMemorySize,
                         FUSED_SMEM);

    // 1) weight split
    wsplit_kernel<<<(ON * KD) / 256, 256>>>(w_deform);

    // 2) fused deformable conv (im2col + GEMM in one kernel)
    {
        dim3 gg(HW / BNT, BN);               // (64, 8)
        fused_dconv_kernel<<<gg, 512, FUSED_SMEM>>>(x, x_off, w_offset, out);
    }

    // 3) GroupNorm
    gn_stats_kernel<<<BN * GN_GROUPS, 256>>>(out);
    gn_norm_kernel<<<(BN * ON * HW / 4) / 256, 256>>>(out, gamma, beta);
}

// round 15
// speedup vs baseline: 1.3949x; 1.3949x over previous
#include <cuda_runtime.h>
#include <cuda_fp16.h>
#include <stdint.h>
#include <math.h>

// Problem constants
#define BN 8
#define CN 256
#define ON 256
#define HN 64
#define WN 64
#define HW 4096
#define K2 9
#define DGN 4
#define CGN 64
#define KD 2304          // CN*K2 (GEMM reduction dim)
#define GN_GROUPS 32
#define GRP_ELEMS 32768
#define EPS 1e-5f

// GEMM tiling (128x64, 256 threads, 8 warps as 4m x 2n; per-warp 32x32)
#define BM 128
#define BNT 64
#define BK 32
#define NCH (KD / BK)        // 72
#define ROWB 80              // padded SMEM row stride (bytes) for 32 fp16
#define T_A (BM * ROWB)      // 10240 (one of hi/lo)
#define T_B (BNT * ROWB)     // 5120  (single fp16 B)
#define STAGE_B (2 * T_A + T_B)       // 25600
#define NSTAGE 3
#define GEMM_SMEM (NSTAGE * STAGE_B)  // 76800

// ---------------------------------------------------------------------------
// Device scratch (B is single fp16 now: col buffer halved)
// ---------------------------------------------------------------------------
__device__ __half g_colf[(size_t)BN * HW * KD];   // 151 MB, [b][hw][kd]
__device__ __half g_wh[(size_t)ON * KD];
__device__ __half g_wl[(size_t)ON * KD];
__device__ float g_mu[BN * GN_GROUPS];
__device__ float g_rstd[BN * GN_GROUPS];

// ---------------------------------------------------------------------------
// PTX helpers (stable sm_80+ features only)
// ---------------------------------------------------------------------------
__device__ __forceinline__ uint32_t smem_u32(const void* p) {
    uint32_t a;
    asm("{ .reg .u64 t; cvta.to.shared.u64 t, %1; cvt.u32.u64 %0, t; }"
        : "=r"(a) : "l"(p));
    return a;
}
__device__ __forceinline__ void cp16(uint32_t s, const void* g) {
    asm volatile("cp.async.cg.shared.global [%0], [%1], 16;"
                 :: "r"(s), "l"(g) : "memory");
}
#define CP_COMMIT() asm volatile("cp.async.commit_group;" ::: "memory")
#define CP_WAIT(n)  asm volatile("cp.async.wait_group %0;" :: "n"(n) : "memory")

__device__ __forceinline__ void ldm_x4(uint32_t* r, uint32_t addr) {
    asm volatile("ldmatrix.sync.aligned.m8n8.x4.shared.b16 {%0,%1,%2,%3}, [%4];"
                 : "=r"(r[0]), "=r"(r[1]), "=r"(r[2]), "=r"(r[3]) : "r"(addr));
}
__device__ __forceinline__ void mma_f16(float* c, const uint32_t* a,
                                        const uint32_t* b) {
    asm volatile(
        "mma.sync.aligned.m16n8k16.row.col.f32.f16.f16.f32 "
        "{%0,%1,%2,%3}, {%4,%5,%6,%7}, {%8,%9}, {%0,%1,%2,%3};"
        : "+f"(c[0]), "+f"(c[1]), "+f"(c[2]), "+f"(c[3])
        : "r"(a[0]), "r"(a[1]), "r"(a[2]), "r"(a[3]), "r"(b[0]), "r"(b[1]));
}

// ---------------------------------------------------------------------------
// Kernel A: split weights into fp16 hi/lo (captures w to ~2^-24).
// w flat [O][KD], kd = c*9+ky*3+kx.
// ---------------------------------------------------------------------------
__global__ void wsplit_kernel(const float* __restrict__ w)
{
    int i = blockIdx.x * blockDim.x + threadIdx.x;
    float v = w[i];
    __half h = __float2half(v);
    __half l = __float2half(v - __half2float(h));
    g_wh[i] = h;
    g_wl[i] = l;
}

// ---------------------------------------------------------------------------
// Kernel B (v5f): fused offset-projection + deformable im2col, single fp16
// output. Phase 1 / phase 3 structure identical to validated v5; phase 2
// k-outer; one fp16 convert/store per value (no lo plane).
// Output: col[b][hw][kd], kd = g*576 + c*9 + k.
// ---------------------------------------------------------------------------
#define V5HW 16
#define QP   288
#define SROW 289               // uint32 row stride (289 mod 32 == 1)
__global__ void __launch_bounds__(256)
im2col5_kernel(const float* __restrict__ x,
               const float* __restrict__ x_off,
               const float* __restrict__ w_offset)
{
    const int b   = blockIdx.z;
    const int g   = blockIdx.y;
    const int hw0 = blockIdx.x * V5HW;
    const int tid = threadIdx.x;

    __shared__ int      s_i[4][V5HW * 9];
    __shared__ float    s_w[4][V5HW * 9];
    __shared__ uint32_t s_h[V5HW * SROW];    // packed fp16x2 (kd even, kd odd)

    // Phase 1: bilinear params for 16 hw x 9 k (validated math, unchanged)
    if (tid < V5HW * 9) {
        int p   = tid;
        int hwl = p / 9;
        int k   = p - hwl * 9;
        int hw  = hw0 + hwl;
        int h = hw >> 6, w = hw & 63;

        const float* xo = x_off + (size_t)b * 4 * HW + hw;
        float o0 = xo[0], o1 = xo[HW], o2 = xo[2 * HW], o3 = xo[3 * HW];
        const float* wo = w_offset + (size_t)((g * K2 + k) * 2) * 4;
        float offy = wo[0] * o0 + wo[1] * o1 + wo[2] * o2 + wo[3] * o3;
        float offx = wo[4] * o0 + wo[5] * o1 + wo[6] * o2 + wo[7] * o3;

        float py = (float)(h + k / 3 - 1) + offy;
        float px = (float)(w + k % 3 - 1) + offx;
        float fy = floorf(py), fx = floorf(px);
        int y0 = (int)fy, x0 = (int)fx, y1 = y0 + 1, x1 = x0 + 1;
        float wy = py - fy, wx = px - fx;

        float my0 = (y0 >= 0 && y0 < HN) ? 1.f : 0.f;
        float my1 = (y1 >= 0 && y1 < HN) ? 1.f : 0.f;
        float mx0 = (x0 >= 0 && x0 < WN) ? 1.f : 0.f;
        float mx1 = (x1 >= 0 && x1 < WN) ? 1.f : 0.f;
        int y0c = min(max(y0, 0), HN - 1), y1c = min(max(y1, 0), HN - 1);
        int x0c = min(max(x0, 0), WN - 1), x1c = min(max(x1, 0), WN - 1);

        s_i[0][p] = y0c * WN + x0c;
        s_i[1][p] = y0c * WN + x1c;
        s_i[2][p] = y1c * WN + x0c;
        s_i[3][p] = y1c * WN + x1c;
        s_w[0][p] = (1.f - wy) * (1.f - wx) * my0 * mx0;
        s_w[1][p] = (1.f - wy) * wx          * my0 * mx1;
        s_w[2][p] = wy * (1.f - wx)          * my1 * mx0;
        s_w[3][p] = wy * wx                  * my1 * mx1;
    }
    __syncthreads();

    const float* xg = x + ((size_t)(b * CN + g * CGN)) * HW;
    uint16_t* s_h16 = (uint16_t*)s_h;

    // Phase 2 (k-outer): thread = (hwl = tid&15, slot s = tid>>4).
    {
        const int hwl = tid & 15;
        const int s   = tid >> 4;
        const int p   = hwl * 9;

        for (int k = 0; k < 9; k++) {
            int   i0 = s_i[0][p + k], i1 = s_i[1][p + k];
            int   i2 = s_i[2][p + k], i3 = s_i[3][p + k];
            float w0 = s_w[0][p + k], w1 = s_w[1][p + k];
            float w2 = s_w[2][p + k], w3 = s_w[3][p + k];

            #pragma unroll
            for (int jj = 0; jj < 4; jj++) {
                int c = jj * 16 + s;
                const float* xc = xg + (size_t)c * HW;
                float v = w0 * xc[i0] + w1 * xc[i1] +
                          w2 * xc[i2] + w3 * xc[i3];
                __half hb = __float2half(v);
                int kd = c * 9 + k;
                s_h16[hwl * (SROW * 2) + kd] = __half_as_ushort(hb);
            }
        }
    }
    __syncthreads();

    // Phase 3: coalesced writeout, 288-word bursts per hw row.
    uint32_t* gh = (uint32_t*)(g_colf + ((size_t)b * HW) * KD + (size_t)g * 576);
    for (int idx = tid; idx < V5HW * QP; idx += 256) {
        int hwl = idx / QP;
        int q   = idx - hwl * QP;
        size_t goff = (size_t)(hw0 + hwl) * (KD / 2) + q;
        gh[goff] = s_h[hwl * SROW + q];
    }
}

// ---------------------------------------------------------------------------
// Kernel C: mma.sync fp16 GEMM, 2 MMAs per fragment: C = Ah*B + Al*B.
// Race-free 3-stage cp.async pipeline (R13-validated ordering:
// wait -> barrier -> issue -> compute). 256 threads, 2 CTAs/SM.
// ---------------------------------------------------------------------------
__global__ void __launch_bounds__(256, 2)
gemm_mma_kernel(float* __restrict__ out)
{
    extern __shared__ char smem[];
    const uint32_t sb = smem_u32(smem);
    const int tid = threadIdx.x;
    const int wid = tid >> 5, lane = tid & 31;
    const int warp_m = wid & 3;
    const int warp_n = wid >> 2;
    const int m0 = blockIdx.x * BM;
    const int n0 = blockIdx.y * BNT;
    const int b  = blockIdx.z;

    const __half* Ah = g_wh + (size_t)m0 * KD;
    const __half* Al = g_wl + (size_t)m0 * KD;
    const __half* Bf = g_colf + ((size_t)(b * HW + n0)) * KD;

    const int arow0 = tid >> 2,         acs0 = (tid & 3);
    const int arow1 = (tid + 256) >> 2, acs1 = (tid & 3);
    const int brow = tid >> 2, bcs = (tid & 3);

    float c[2][4][4];
    #pragma unroll
    for (int i = 0; i < 2; i++)
        #pragma unroll
        for (int j = 0; j < 4; j++)
            #pragma unroll
            for (int q = 0; q < 4; q++) c[i][j][q] = 0.f;

    auto load_chunk = [&](int ch, int stg) {
        const int k0 = ch * BK;
        uint32_t st = sb + stg * STAGE_B;
        cp16(st + 0 * T_A + arow0 * ROWB + acs0 * 16, Ah + (size_t)arow0 * KD + k0 + acs0 * 8);
        cp16(st + 0 * T_A + arow1 * ROWB + acs1 * 16, Ah + (size_t)arow1 * KD + k0 + acs1 * 8);
        cp16(st + 1 * T_A + arow0 * ROWB + acs0 * 16, Al + (size_t)arow0 * KD + k0 + acs0 * 8);
        cp16(st + 1 * T_A + arow1 * ROWB + acs1 * 16, Al + (size_t)arow1 * KD + k0 + acs1 * 8);
        cp16(st + 2 * T_A + brow * ROWB + bcs * 16,   Bf + (size_t)brow * KD + k0 + bcs * 8);
        CP_COMMIT();
    };

    // Prologue: chunks 0 and 1 into stages 0 and 1.
    load_chunk(0, 0);
    load_chunk(1, 1);

    for (int ch = 0; ch < NCH; ch++) {
        // 1) ensure this iteration's stage (group ch) has landed
        if (ch + 1 < NCH) {
            CP_WAIT(1);
        } else {
            CP_WAIT(0);
        }
        // 2) barrier: all warps are done with iteration ch-1's stage
        __syncthreads();
        // 3) only now overwrite stage (ch+2)%3 == (ch-1)%3
        if (ch + 2 < NCH) {
            load_chunk(ch + 2, (ch + 2) % NSTAGE);
        }

        // 4) compute on stage ch%3
        const uint32_t st = sb + (ch % NSTAGE) * STAGE_B;
        #pragma unroll
        for (int ks = 0; ks < 2; ks++) {
            uint32_t a_off = (uint32_t)((warp_m * 32 + (lane & 15)) * ROWB
                                        + ks * 32 + ((lane >> 4) << 4));
            uint32_t ah[2][4], al[2][4];
            #pragma unroll
            for (int mf = 0; mf < 2; mf++) {
                ldm_x4(ah[mf], st + 0 * T_A + a_off + mf * 16 * ROWB);
                ldm_x4(al[mf], st + 1 * T_A + a_off + mf * 16 * ROWB);
            }
            uint32_t b_off = (uint32_t)((warp_n * 32 + (lane & 7) + ((lane >> 4) << 3)) * ROWB
                                        + ks * 32 + (((lane >> 3) & 1) << 4));
            uint32_t bh[4][2];
            #pragma unroll
            for (int nfp = 0; nfp < 2; nfp++) {
                uint32_t r[4];
                ldm_x4(r, st + 2 * T_A + b_off + nfp * 16 * ROWB);
                bh[nfp * 2][0] = r[0]; bh[nfp * 2][1] = r[1];
                bh[nfp * 2 + 1][0] = r[2]; bh[nfp * 2 + 1][1] = r[3];
            }
            #pragma unroll
            for (int mf = 0; mf < 2; mf++)
                #pragma unroll
                for (int nf = 0; nf < 4; nf++) {
                    mma_f16(c[mf][nf], ah[mf], bh[nf]);
                    mma_f16(c[mf][nf], al[mf], bh[nf]);
                }
        }
    }

    #pragma unroll
    for (int mf = 0; mf < 2; mf++)
        #pragma unroll
        for (int nf = 0; nf < 4; nf++) {
            int row = m0 + warp_m * 32 + mf * 16 + (lane >> 2);
            int col = n0 + warp_n * 32 + nf * 8 + 2 * (lane & 3);
            float* op0 = out + ((size_t)(b * ON + row)) * HW + col;
            float* op1 = out + ((size_t)(b * ON + row + 8)) * HW + col;
            *(float2*)op0 = make_float2(c[mf][nf][0], c[mf][nf][1]);
            *(float2*)op1 = make_float2(c[mf][nf][2], c[mf][nf][3]);
        }
}

// ---------------------------------------------------------------------------
// GroupNorm stats + normalize (validated)
// ---------------------------------------------------------------------------
__global__ void gn_stats_kernel(const float* __restrict__ y)
{
    const int bg = blockIdx.x;
    const float* p = y + (size_t)bg * GRP_ELEMS;
    float s = 0.f, ss = 0.f;
    for (int i = threadIdx.x * 4; i < GRP_ELEMS; i += blockDim.x * 4) {
        float4 v = *(const float4*)(p + i);
        s  += v.x + v.y + v.z + v.w;
        ss += v.x * v.x + v.y * v.y + v.z * v.z + v.w * v.w;
    }
    #pragma unroll
    for (int off = 16; off > 0; off >>= 1) {
        s  += __shfl_down_sync(0xffffffffu, s,  off);
        ss += __shfl_down_sync(0xffffffffu, ss, off);
    }
    __shared__ float sh_s[8], sh_ss[8];
    int wid = threadIdx.x >> 5, lid = threadIdx.x & 31;
    if (lid == 0) { sh_s[wid] = s; sh_ss[wid] = ss; }
    __syncthreads();
    if (wid == 0) {
        s  = (lid < 8) ? sh_s[lid]  : 0.f;
        ss = (lid < 8) ? sh_ss[lid] : 0.f;
        #pragma unroll
        for (int off = 4; off > 0; off >>= 1) {
            s  += __shfl_down_sync(0xffffffffu, s,  off);
            ss += __shfl_down_sync(0xffffffffu, ss, off);
        }
        if (lid == 0) {
            float mu  = s * (1.f / GRP_ELEMS);
            float var = ss * (1.f / GRP_ELEMS) - mu * mu;
            g_mu[bg]   = mu;
            g_rstd[bg] = rsqrtf(var + EPS);
        }
    }
}

__global__ void gn_norm_kernel(float* __restrict__ y,
                               const float* __restrict__ gamma,
                               const float* __restrict__ beta)
{
    int idx = blockIdx.x * blockDim.x + threadIdx.x;
    int bg = idx >> 13;
    int c  = (idx >> 10) & 255;
    float mu = g_mu[bg];
    float r  = g_rstd[bg];
    float a  = r * gamma[c];
    float bb = beta[c] - mu * a;
    float4 v = *(float4*)(y + (size_t)idx * 4);
    v.x = fmaxf(fmaf(v.x, a, bb), 0.f);
    v.y = fmaxf(fmaf(v.y, a, bb), 0.f);
    v.z = fmaxf(fmaf(v.z, a, bb), 0.f);
    v.w = fmaxf(fmaf(v.w, a, bb), 0.f);
    *(float4*)(y + (size_t)idx * 4) = v;
}

// ---------------------------------------------------------------------------
// Launcher (full-batch, R13 structure)
// ---------------------------------------------------------------------------
extern "C" void kernel_launch(void* const* d_in, const int* in_sizes, int n_in,
                              void* d_out, int out_size)
{
    const float* x        = (const float*)d_in[0];
    const float* x_off    = (const float*)d_in[1];
    const float* w_offset = (const float*)d_in[2];
    const float* w_deform = (const float*)d_in[3];
    const float* gamma    = (const float*)d_in[4];
    const float* beta     = (const float*)d_in[5];
    float* out = (float*)d_out;

    cudaFuncSetAttribute(gemm_mma_kernel,
                         cudaFuncAttributeMaxDynamicSharedMemorySize,
                         GEMM_SMEM);

    // 1) weight split (fp16 hi/lo)
    wsplit_kernel<<<(ON * KD) / 256, 256>>>(w_deform);

    // 2) deformable im2col v5f (single fp16 col)
    {
        dim3 gi(HW / V5HW, DGN, BN);         // (256, 4, 8)
        im2col5_kernel<<<gi, 256>>>(x, x_off, w_offset);
    }

    // 3) tensor-core GEMM (2-MMA fp16 split, race-free 3-stage)
    {
        dim3 gg(ON / BM, HW / BNT, BN);      // (2, 64, 8)
        gemm_mma_kernel<<<gg, 256, GEMM_SMEM>>>(out);
    }

    // 4) GroupNorm
    gn_stats_kernel<<<BN * GN_GROUPS, 256>>>(out);
    gn_norm_kernel<<<(BN * ON * HW / 4) / 256, 256>>>(out, gamma, beta);
}

// round 16
// speedup vs baseline: 1.9029x; 1.3642x over previous
#include <cuda_runtime.h>
#include <cuda_fp16.h>
#include <stdint.h>
#include <math.h>

// Problem constants
#define BN 8
#define CN 256
#define ON 256
#define HN 64
#define WN 64
#define HW 4096
#define K2 9
#define DGN 4
#define CGN 64
#define KD 2304          // CN*K2 (GEMM reduction dim)
#define GN_GROUPS 32
#define GRP_ELEMS 32768
#define EPS 1e-5f

// GEMM tiling (128x64, 256 threads, 8 warps as 4m x 2n; per-warp 32x32)
#define BM 128
#define BNT 64
#define BK 32
#define NCH (KD / BK)        // 72
#define ROWB 80              // padded SMEM row stride (bytes) for 32 fp16
#define T_A (BM * ROWB)      // 10240 (single fp16 A)
#define T_B (BNT * ROWB)     // 5120  (single fp16 B)
#define STAGE_B (T_A + T_B)           // 15360
#define NSTAGE 3
#define GEMM_SMEM (NSTAGE * STAGE_B)  // 46080

// ---------------------------------------------------------------------------
// Device scratch
// ---------------------------------------------------------------------------
__device__ __half g_colf[(size_t)BN * HW * KD];   // 151 MB, [b][hw][kd]
__device__ __half g_wh[(size_t)ON * KD];          // single fp16 weights
__device__ float g_mu[BN * GN_GROUPS];
__device__ float g_rstd[BN * GN_GROUPS];

// ---------------------------------------------------------------------------
// PTX helpers (stable sm_80+ features only)
// ---------------------------------------------------------------------------
__device__ __forceinline__ uint32_t smem_u32(const void* p) {
    uint32_t a;
    asm("{ .reg .u64 t; cvta.to.shared.u64 t, %1; cvt.u32.u64 %0, t; }"
        : "=r"(a) : "l"(p));
    return a;
}
__device__ __forceinline__ void cp16(uint32_t s, const void* g) {
    asm volatile("cp.async.cg.shared.global [%0], [%1], 16;"
                 :: "r"(s), "l"(g) : "memory");
}
#define CP_COMMIT() asm volatile("cp.async.commit_group;" ::: "memory")
#define CP_WAIT(n)  asm volatile("cp.async.wait_group %0;" :: "n"(n) : "memory")

__device__ __forceinline__ void ldm_x4(uint32_t* r, uint32_t addr) {
    asm volatile("ldmatrix.sync.aligned.m8n8.x4.shared.b16 {%0,%1,%2,%3}, [%4];"
                 : "=r"(r[0]), "=r"(r[1]), "=r"(r[2]), "=r"(r[3]) : "r"(addr));
}
__device__ __forceinline__ void mma_f16(float* c, const uint32_t* a,
                                        const uint32_t* b) {
    asm volatile(
        "mma.sync.aligned.m16n8k16.row.col.f32.f16.f16.f32 "
        "{%0,%1,%2,%3}, {%4,%5,%6,%7}, {%8,%9}, {%0,%1,%2,%3};"
        : "+f"(c[0]), "+f"(c[1]), "+f"(c[2]), "+f"(c[3])
        : "r"(a[0]), "r"(a[1]), "r"(a[2]), "r"(a[3]), "r"(b[0]), "r"(b[1]));
}

// ---------------------------------------------------------------------------
// Kernel A: convert weights to fp16. w flat [O][KD], kd = c*9+ky*3+kx.
// ---------------------------------------------------------------------------
__global__ void wsplit_kernel(const float* __restrict__ w)
{
    int i = blockIdx.x * blockDim.x + threadIdx.x;
    g_wh[i] = __float2half(w[i]);
}

// ---------------------------------------------------------------------------
// Kernel B (v5f): fused offset-projection + deformable im2col, single fp16
// output (validated R15 kernel, unchanged).
// Output: col[b][hw][kd], kd = g*576 + c*9 + k.
// ---------------------------------------------------------------------------
#define V5HW 16
#define QP   288
#define SROW 289               // uint32 row stride (289 mod 32 == 1)
__global__ void __launch_bounds__(256)
im2col5_kernel(const float* __restrict__ x,
               const float* __restrict__ x_off,
               const float* __restrict__ w_offset)
{
    const int b   = blockIdx.z;
    const int g   = blockIdx.y;
    const int hw0 = blockIdx.x * V5HW;
    const int tid = threadIdx.x;

    __shared__ int      s_i[4][V5HW * 9];
    __shared__ float    s_w[4][V5HW * 9];
    __shared__ uint32_t s_h[V5HW * SROW];    // packed fp16x2 (kd even, kd odd)

    // Phase 1: bilinear params for 16 hw x 9 k (validated math, unchanged)
    if (tid < V5HW * 9) {
        int p   = tid;
        int hwl = p / 9;
        int k   = p - hwl * 9;
        int hw  = hw0 + hwl;
        int h = hw >> 6, w = hw & 63;

        const float* xo = x_off + (size_t)b * 4 * HW + hw;
        float o0 = xo[0], o1 = xo[HW], o2 = xo[2 * HW], o3 = xo[3 * HW];
        const float* wo = w_offset + (size_t)((g * K2 + k) * 2) * 4;
        float offy = wo[0] * o0 + wo[1] * o1 + wo[2] * o2 + wo[3] * o3;
        float offx = wo[4] * o0 + wo[5] * o1 + wo[6] * o2 + wo[7] * o3;

        float py = (float)(h + k / 3 - 1) + offy;
        float px = (float)(w + k % 3 - 1) + offx;
        float fy = floorf(py), fx = floorf(px);
        int y0 = (int)fy, x0 = (int)fx, y1 = y0 + 1, x1 = x0 + 1;
        float wy = py - fy, wx = px - fx;

        float my0 = (y0 >= 0 && y0 < HN) ? 1.f : 0.f;
        float my1 = (y1 >= 0 && y1 < HN) ? 1.f : 0.f;
        float mx0 = (x0 >= 0 && x0 < WN) ? 1.f : 0.f;
        float mx1 = (x1 >= 0 && x1 < WN) ? 1.f : 0.f;
        int y0c = min(max(y0, 0), HN - 1), y1c = min(max(y1, 0), HN - 1);
        int x0c = min(max(x0, 0), WN - 1), x1c = min(max(x1, 0), WN - 1);

        s_i[0][p] = y0c * WN + x0c;
        s_i[1][p] = y0c * WN + x1c;
        s_i[2][p] = y1c * WN + x0c;
        s_i[3][p] = y1c * WN + x1c;
        s_w[0][p] = (1.f - wy) * (1.f - wx) * my0 * mx0;
        s_w[1][p] = (1.f - wy) * wx          * my0 * mx1;
        s_w[2][p] = wy * (1.f - wx)          * my1 * mx0;
        s_w[3][p] = wy * wx                  * my1 * mx1;
    }
    __syncthreads();

    const float* xg = x + ((size_t)(b * CN + g * CGN)) * HW;
    uint16_t* s_h16 = (uint16_t*)s_h;

    // Phase 2 (k-outer): thread = (hwl = tid&15, slot s = tid>>4).
    {
        const int hwl = tid & 15;
        const int s   = tid >> 4;
        const int p   = hwl * 9;

        for (int k = 0; k < 9; k++) {
            int   i0 = s_i[0][p + k], i1 = s_i[1][p + k];
            int   i2 = s_i[2][p + k], i3 = s_i[3][p + k];
            float w0 = s_w[0][p + k], w1 = s_w[1][p + k];
            float w2 = s_w[2][p + k], w3 = s_w[3][p + k];

            #pragma unroll
            for (int jj = 0; jj < 4; jj++) {
                int c = jj * 16 + s;
                const float* xc = xg + (size_t)c * HW;
                float v = w0 * xc[i0] + w1 * xc[i1] +
                          w2 * xc[i2] + w3 * xc[i3];
                __half hb = __float2half(v);
                int kd = c * 9 + k;
                s_h16[hwl * (SROW * 2) + kd] = __half_as_ushort(hb);
            }
        }
    }
    __syncthreads();

    // Phase 3: coalesced writeout, 288-word bursts per hw row.
    uint32_t* gh = (uint32_t*)(g_colf + ((size_t)b * HW) * KD + (size_t)g * 576);
    for (int idx = tid; idx < V5HW * QP; idx += 256) {
        int hwl = idx / QP;
        int q   = idx - hwl * QP;
        size_t goff = (size_t)(hw0 + hwl) * (KD / 2) + q;
        gh[goff] = s_h[hwl * SROW + q];
    }
}

// ---------------------------------------------------------------------------
// Kernel C: plain fp16 mma.sync GEMM, 1 MMA per fragment.
// Race-free 3-stage cp.async pipeline (validated ordering:
// wait -> barrier -> issue -> compute). 256 threads, 2 CTAs/SM.
// ---------------------------------------------------------------------------
__global__ void __launch_bounds__(256, 2)
gemm_mma_kernel(float* __restrict__ out)
{
    extern __shared__ char smem[];
    const uint32_t sb = smem_u32(smem);
    const int tid = threadIdx.x;
    const int wid = tid >> 5, lane = tid & 31;
    const int warp_m = wid & 3;
    const int warp_n = wid >> 2;
    const int m0 = blockIdx.x * BM;
    const int n0 = blockIdx.y * BNT;
    const int b  = blockIdx.z;

    const __half* Ah = g_wh + (size_t)m0 * KD;
    const __half* Bf = g_colf + ((size_t)(b * HW + n0)) * KD;

    const int arow0 = tid >> 2,         acs0 = (tid & 3);
    const int arow1 = (tid + 256) >> 2, acs1 = (tid & 3);
    const int brow = tid >> 2, bcs = (tid & 3);

    float c[2][4][4];
    #pragma unroll
    for (int i = 0; i < 2; i++)
        #pragma unroll
        for (int j = 0; j < 4; j++)
            #pragma unroll
            for (int q = 0; q < 4; q++) c[i][j][q] = 0.f;

    auto load_chunk = [&](int ch, int stg) {
        const int k0 = ch * BK;
        uint32_t st = sb + stg * STAGE_B;
        cp16(st + arow0 * ROWB + acs0 * 16, Ah + (size_t)arow0 * KD + k0 + acs0 * 8);
        cp16(st + arow1 * ROWB + acs1 * 16, Ah + (size_t)arow1 * KD + k0 + acs1 * 8);
        cp16(st + T_A + brow * ROWB + bcs * 16, Bf + (size_t)brow * KD + k0 + bcs * 8);
        CP_COMMIT();
    };

    // Prologue: chunks 0 and 1 into stages 0 and 1.
    load_chunk(0, 0);
    load_chunk(1, 1);

    for (int ch = 0; ch < NCH; ch++) {
        // 1) ensure this iteration's stage (group ch) has landed
        if (ch + 1 < NCH) {
            CP_WAIT(1);
        } else {
            CP_WAIT(0);
        }
        // 2) barrier: all warps are done with iteration ch-1's stage
        __syncthreads();
        // 3) only now overwrite stage (ch+2)%3 == (ch-1)%3
        if (ch + 2 < NCH) {
            load_chunk(ch + 2, (ch + 2) % NSTAGE);
        }

        // 4) compute on stage ch%3
        const uint32_t st = sb + (ch % NSTAGE) * STAGE_B;
        #pragma unroll
        for (int ks = 0; ks < 2; ks++) {
            uint32_t a_off = (uint32_t)((warp_m * 32 + (lane & 15)) * ROWB
                                        + ks * 32 + ((lane >> 4) << 4));
            uint32_t ah[2][4];
            #pragma unroll
            for (int mf = 0; mf < 2; mf++) {
                ldm_x4(ah[mf], st + a_off + mf * 16 * ROWB);
            }
            uint32_t b_off = (uint32_t)((warp_n * 32 + (lane & 7) + ((lane >> 4) << 3)) * ROWB
                                        + ks * 32 + (((lane >> 3) & 1) << 4));
            uint32_t bh[4][2];
            #pragma unroll
            for (int nfp = 0; nfp < 2; nfp++) {
                uint32_t r[4];
                ldm_x4(r, st + T_A + b_off + nfp * 16 * ROWB);
                bh[nfp * 2][0] = r[0]; bh[nfp * 2][1] = r[1];
                bh[nfp * 2 + 1][0] = r[2]; bh[nfp * 2 + 1][1] = r[3];
            }
            #pragma unroll
            for (int mf = 0; mf < 2; mf++)
                #pragma unroll
                for (int nf = 0; nf < 4; nf++) {
                    mma_f16(c[mf][nf], ah[mf], bh[nf]);
                }
        }
    }

    #pragma unroll
    for (int mf = 0; mf < 2; mf++)
        #pragma unroll
        for (int nf = 0; nf < 4; nf++) {
            int row = m0 + warp_m * 32 + mf * 16 + (lane >> 2);
            int col = n0 + warp_n * 32 + nf * 8 + 2 * (lane & 3);
            float* op0 = out + ((size_t)(b * ON + row)) * HW + col;
            float* op1 = out + ((size_t)(b * ON + row + 8)) * HW + col;
            *(float2*)op0 = make_float2(c[mf][nf][0], c[mf][nf][1]);
            *(float2*)op1 = make_float2(c[mf][nf][2], c[mf][nf][3]);
        }
}

// ---------------------------------------------------------------------------
// GroupNorm stats + normalize (validated)
// ---------------------------------------------------------------------------
__global__ void gn_stats_kernel(const float* __restrict__ y)
{
    const int bg = blockIdx.x;
    const float* p = y + (size_t)bg * GRP_ELEMS;
    float s = 0.f, ss = 0.f;
    for (int i = threadIdx.x * 4; i < GRP_ELEMS; i += blockDim.x * 4) {
        float4 v = *(const float4*)(p + i);
        s  += v.x + v.y + v.z + v.w;
        ss += v.x * v.x + v.y * v.y + v.z * v.z + v.w * v.w;
    }
    #pragma unroll
    for (int off = 16; off > 0; off >>= 1) {
        s  += __shfl_down_sync(0xffffffffu, s,  off);
        ss += __shfl_down_sync(0xffffffffu, ss, off);
    }
    __shared__ float sh_s[8], sh_ss[8];
    int wid = threadIdx.x >> 5, lid = threadIdx.x & 31;
    if (lid == 0) { sh_s[wid] = s; sh_ss[wid] = ss; }
    __syncthreads();
    if (wid == 0) {
        s  = (lid < 8) ? sh_s[lid]  : 0.f;
        ss = (lid < 8) ? sh_ss[lid] : 0.f;
        #pragma unroll
        for (int off = 4; off > 0; off >>= 1) {
            s  += __shfl_down_sync(0xffffffffu, s,  off);
            ss += __shfl_down_sync(0xffffffffu, ss, off);
        }
        if (lid == 0) {
            float mu  = s * (1.f / GRP_ELEMS);
            float var = ss * (1.f / GRP_ELEMS) - mu * mu;
            g_mu[bg]   = mu;
            g_rstd[bg] = rsqrtf(var + EPS);
        }
    }
}

__global__ void gn_norm_kernel(float* __restrict__ y,
                               const float* __restrict__ gamma,
                               const float* __restrict__ beta)
{
    int idx = blockIdx.x * blockDim.x + threadIdx.x;
    int bg = idx >> 13;
    int c  = (idx >> 10) & 255;
    float mu = g_mu[bg];
    float r  = g_rstd[bg];
    float a  = r * gamma[c];
    float bb = beta[c] - mu * a;
    float4 v = *(float4*)(y + (size_t)idx * 4);
    v.x = fmaxf(fmaf(v.x, a, bb), 0.f);
    v.y = fmaxf(fmaf(v.y, a, bb), 0.f);
    v.z = fmaxf(fmaf(v.z, a, bb), 0.f);
    v.w = fmaxf(fmaf(v.w, a, bb), 0.f);
    *(float4*)(y + (size_t)idx * 4) = v;
}

// ---------------------------------------------------------------------------
// Launcher (full-batch, validated structure)
// ---------------------------------------------------------------------------
extern "C" void kernel_launch(void* const* d_in, const int* in_sizes, int n_in,
                              void* d_out, int out_size)
{
    const float* x        = (const float*)d_in[0];
    const float* x_off    = (const float*)d_in[1];
    const float* w_offset = (const float*)d_in[2];
    const float* w_deform = (const float*)d_in[3];
    const float* gamma    = (const float*)d_in[4];
    const float* beta     = (const float*)d_in[5];
    float* out = (float*)d_out;

    cudaFuncSetAttribute(gemm_mma_kernel,
                         cudaFuncAttributeMaxDynamicSharedMemorySize,
                         GEMM_SMEM);

    // 1) weight convert (fp16)
    wsplit_kernel<<<(ON * KD) / 256, 256>>>(w_deform);

    // 2) deformable im2col v5f (single fp16 col)
    {
        dim3 gi(HW / V5HW, DGN, BN);         // (256, 4, 8)
        im2col5_kernel<<<gi, 256>>>(x, x_off, w_offset);
    }

    // 3) tensor-core GEMM (plain fp16, 1 MMA, race-free 3-stage)
    {
        dim3 gg(ON / BM, HW / BNT, BN);      // (2, 64, 8)
        gemm_mma_kernel<<<gg, 256, GEMM_SMEM>>>(out);
    }

    // 4) GroupNorm
    gn_stats_kernel<<<BN * GN_GROUPS, 256>>>(out);
    gn_norm_kernel<<<(BN * ON * HW / 4) / 256, 256>>>(out, gamma, beta);
}